// round 16
// baseline (speedup 1.0000x reference)
#include <cuda_runtime.h>
#include <cuda_fp16.h>
#include <cstdint>

// MotilityModel, fully tensor-core (R13 base). R16: single barrier per tile —
// epilogue software-pipelined across tiles (sred/fred double-buffered, A(j+1)
// staged pre-barrier), fp16 A prefetch (8 regs).
//   h = cs @ W1^T + b1 ; h = LN(h)*gamma+beta ; relu ; out = h @ W2^T + b2
// N=500000, CS=64, H=256, S=3, fp32 in/out.

#define N_CELLS 500000
#define TILE_M  64
#define T_TILES ((N_CELLS + TILE_M - 1) / TILE_M)   // 7813
#define THREADS 256                                  // 8 warps

#define ASTH 72   // A row stride in halfs (144B): ldmatrix conflict-free

// ---- smem layout (float offsets) ----
#define W1F_OFF 0
#define W1F_F   8192                     // 32KB fp16 B fragment-major
#define AH_OFF  (W1F_OFF + W1F_F)        // A fp16 [2][64][ASTH] halfs
#define AH_BUF_F (TILE_M * ASTH / 2)     // 2304 floats per buffer
#define AH_F    (2 * AH_BUF_F)
#define B1_OFF  (AH_OFF + AH_F)          // b1 [256]
#define PGB_OFF (B1_OFF + 256)           // [128 colp] float4 {g0,g1,be0,be1}
#define B2_OFF  (PGB_OFF + 512)
#define SR_OFF  (B2_OFF + 4)             // [2 buf][4 ng][64 rows] float2
#define SRBUF2  256                      // float2 per buffer
#define FR_OFF  (SR_OFF + 1024)          // [2 buf][4 ng][64 rows][4] float
#define FRBUF   1024
#define SMEM_F  (FR_OFF + 2048)          // 16644 floats = 66576 B

typedef unsigned long long ull;

__device__ __forceinline__ uint32_t h2(float lo, float hi) {
    __half2 h = __floats2half2_rn(lo, hi);
    return *reinterpret_cast<uint32_t*>(&h);
}

// ---- packed f32x2 helpers ----
__device__ __forceinline__ ull pk2(float lo, float hi) {
    ull r; asm("mov.b64 %0, {%1, %2};" : "=l"(r) : "f"(lo), "f"(hi)); return r;
}
__device__ __forceinline__ void upk2(ull p, float& lo, float& hi) {
    asm("mov.b64 {%0, %1}, %2;" : "=f"(lo), "=f"(hi) : "l"(p));
}
__device__ __forceinline__ ull f2fma(ull a, ull b, ull c) {
    ull d; asm("fma.rn.f32x2 %0, %1, %2, %3;" : "=l"(d) : "l"(a), "l"(b), "l"(c)); return d;
}
__device__ __forceinline__ ull f2add(ull a, ull b) {
    ull d; asm("add.rn.f32x2 %0, %1, %2;" : "=l"(d) : "l"(a), "l"(b)); return d;
}
__device__ __forceinline__ ull f2mul(ull a, ull b) {
    ull d; asm("mul.rn.f32x2 %0, %1, %2;" : "=l"(d) : "l"(a), "l"(b)); return d;
}
// relu fused into fp16x2 convert
__device__ __forceinline__ uint32_t h2relu(ull vp) {
    float lo, hi; upk2(vp, lo, hi);
    uint32_t r;
    asm("cvt.rn.relu.f16x2.f32 %0, %1, %2;" : "=r"(r) : "f"(hi), "f"(lo));
    return r;
}

#define MMA_F16(c, a0, a1, a2, a3, bv0, bv1) \
    asm volatile("mma.sync.aligned.m16n8k16.row.col.f32.f16.f16.f32 " \
        "{%0,%1,%2,%3}, {%4,%5,%6,%7}, {%8,%9}, {%0,%1,%2,%3};" \
        : "+f"((c)[0]), "+f"((c)[1]), "+f"((c)[2]), "+f"((c)[3]) \
        : "r"(a0), "r"(a1), "r"(a2), "r"(a3), "r"(bv0), "r"(bv1))

#define LDMX4(r0, r1, r2, r3, addr) \
    asm volatile("ldmatrix.sync.aligned.m8n8.x4.shared.b16 {%0,%1,%2,%3}, [%4];" \
        : "=r"(r0), "=r"(r1), "=r"(r2), "=r"(r3) : "r"(addr))

struct TrueT  { static constexpr bool value = true;  };
struct FalseT { static constexpr bool value = false; };

__global__ void __launch_bounds__(THREADS, 2) motility_mma_kernel(
    const float* __restrict__ cs,   const float* __restrict__ W1,
    const float* __restrict__ b1,   const float* __restrict__ gamma,
    const float* __restrict__ beta, const float* __restrict__ W2,
    const float* __restrict__ b2,   float* __restrict__ out)
{
    extern __shared__ float sm[];
    float* W1f  = sm + W1F_OFF;
    float* b1s  = sm + B1_OFF;
    float* pgb  = sm + PGB_OFF;
    float* b2s  = sm + B2_OFF;
    float2* sr2 = reinterpret_cast<float2*>(sm + SR_OFF);   // [2][4ng][64]
    float* fred = sm + FR_OFF;                              // [2][4ng][64][4]

    const int tid  = threadIdx.x;
    const int lane = tid & 31;
    const int warp = tid >> 5;          // 0..7
    const int g    = lane >> 2;         // 0..7
    const int tg   = lane & 3;          // 0..3
    const int half    = warp & 1;       // rows half*32..+31 (own barrier)
    const int n_group = warp >> 1;      // cols n_group*64..+63
    const int hwtid   = n_group * 32 + lane;   // 0..127 within half
    const int bid  = blockIdx.x;
    const int GRID = gridDim.x;

    const int barid = 1 + half;
    #define BARH() asm volatile("bar.sync %0, 128;" :: "r"(barid) : "memory")

    const uint32_t Au = (uint32_t)__cvta_generic_to_shared(sm + AH_OFF);
    const uint32_t lm_lane_off = (uint32_t)(lane & 15) * (ASTH * 2) + (uint32_t)(lane >> 4) * 16;

    const int st_row = half * 32 + (hwtid >> 2);
    const int st_cq  = (hwtid & 3) * 16;
    const uint32_t st_dst = Au + (uint32_t)(st_row * ASTH + st_cq) * 2;

    const int nT = (T_TILES - 1 - bid) / GRID + 1;

    // ---- W2 fp16 B-fragments for GEMM2 ----
    uint32_t w2f[4][2];
    #pragma unroll
    for (int q = 0; q < 4; q++) {
        if (g < 3) {
            const float* wr = W2 + g * 256 + n_group * 64 + q * 16 + tg * 2;
            w2f[q][0] = h2(wr[0], wr[1]);
            w2f[q][1] = h2(wr[8], wr[9]);
        } else {
            w2f[q][0] = 0u; w2f[q][1] = 0u;
        }
    }

    // ---- stage W1 as fp16 fragments (once) ----
    #pragma unroll
    for (int i = 0; i < 8; i++) {
        int idx = tid + i * THREADS;            // 0..2047
        int li  = idx & 31;
        int rg  = (idx >> 5) & 3;
        int ng  = (idx >> 7) & 3;
        int kk  = idx >> 9;
        int gg = li >> 2, tt = li & 3;
        int k0 = kk * 16 + tt * 2;
        int ca = ng * 64 + (rg * 2) * 8 + gg;
        int cb = ca + 8;
        uint4 v;
        v.x = h2(W1[ca * 64 + k0],     W1[ca * 64 + k0 + 1]);
        v.y = h2(W1[ca * 64 + k0 + 8], W1[ca * 64 + k0 + 9]);
        v.z = h2(W1[cb * 64 + k0],     W1[cb * 64 + k0 + 1]);
        v.w = h2(W1[cb * 64 + k0 + 8], W1[cb * 64 + k0 + 9]);
        reinterpret_cast<uint4*>(W1f)[idx] = v;
    }
    b1s[tid] = b1[tid];
    if (tid < 128) {
        int c0 = 2 * tid;
        reinterpret_cast<float4*>(pgb)[tid] =
            make_float4(gamma[c0], gamma[c0 + 1], beta[c0], beta[c0 + 1]);
    }
    if (tid < 3) b2s[tid] = b2[tid];

    // ---- A prefetch held as fp16 (8 regs) ----
    uint32_t pf16[8];
    auto ldgA = [&](int j) {
        long tile = (long)bid + (long)j * GRID;
        long cell = tile * TILE_M + st_row;
        if (j < nT && cell < N_CELLS) {
            const float4* src = reinterpret_cast<const float4*>(cs + cell * 64 + st_cq);
            float4 v0 = src[0], v1 = src[1], v2 = src[2], v3 = src[3];
            pf16[0] = h2(v0.x, v0.y); pf16[1] = h2(v0.z, v0.w);
            pf16[2] = h2(v1.x, v1.y); pf16[3] = h2(v1.z, v1.w);
            pf16[4] = h2(v2.x, v2.y); pf16[5] = h2(v2.z, v2.w);
            pf16[6] = h2(v3.x, v3.y); pf16[7] = h2(v3.z, v3.w);
        } else {
            #pragma unroll
            for (int i = 0; i < 8; i++) pf16[i] = 0u;
        }
    };
    auto stsA = [&](int buf) {
        uint32_t d0 = st_dst + (uint32_t)buf * (AH_BUF_F * 4);
        asm volatile("st.shared.v4.b32 [%0], {%1,%2,%3,%4};"
                     :: "r"(d0), "r"(pf16[0]), "r"(pf16[1]), "r"(pf16[2]), "r"(pf16[3]) : "memory");
        asm volatile("st.shared.v4.b32 [%0], {%1,%2,%3,%4};"
                     :: "r"(d0 + 16), "r"(pf16[4]), "r"(pf16[5]), "r"(pf16[6]), "r"(pf16[7]) : "memory");
    };

    ldgA(0);
    stsA(0);

    // ---- trivial-affine detection (full-CTA barrier; covers all staging) ----
    int nontriv = (b1[tid] != 0.0f) | (gamma[tid] != 1.0f) | (beta[tid] != 0.0f);
    if (tid < 3) nontriv |= (b2[tid] != 0.0f);
    const bool trivial = (__syncthreads_or(nontriv) == 0);

    const uint4* Bf = reinterpret_cast<const uint4*>(W1f) + n_group * 128 + lane;

    auto runloop = [&](auto trivc) {
        constexpr bool TRIV = decltype(trivc)::value;

        // out phase for tile index jj (reads fred buffer jj&1)
        auto out_phase = [&](int jj) {
            if (hwtid < 96) {
                long tilep = (long)bid + (long)jj * GRID;
                int row = half * 32 + hwtid / 3;
                int s   = hwtid - (hwtid / 3) * 3;
                long cell = tilep * TILE_M + row;
                if (cell < N_CELLS) {
                    const float* fr = fred + (jj & 1) * FRBUF;
                    float v = fr[row * 4 + s] + fr[256 + row * 4 + s]
                            + fr[512 + row * 4 + s] + fr[768 + row * 4 + s];
                    if constexpr (!TRIV) v += b2s[s];
                    out[tilep * (TILE_M * 3) + row * 3 + s] = v;
                }
            }
        };

        for (int j = 0; j < nT; j++) {
            // ---- prefetch A(j+1) early; latency covered by GEMM1 ----
            ldgA(j + 1);

            // ---- acc init ----
            float acc[2][8][4];
            if constexpr (TRIV) {
                #pragma unroll
                for (int nt = 0; nt < 8; nt++)
                    #pragma unroll
                    for (int mt = 0; mt < 2; mt++)
                        #pragma unroll
                        for (int qq = 0; qq < 4; qq++) acc[mt][nt][qq] = 0.0f;
            } else {
                #pragma unroll
                for (int nt = 0; nt < 8; nt++) {
                    int colp = n_group * 32 + nt * 4 + tg;
                    float2 bv = reinterpret_cast<const float2*>(b1s)[colp];
                    #pragma unroll
                    for (int mt = 0; mt < 2; mt++) {
                        acc[mt][nt][0] = bv.x; acc[mt][nt][1] = bv.y;
                        acc[mt][nt][2] = bv.x; acc[mt][nt][3] = bv.y;
                    }
                }
            }

            // ---- GEMM1: rows half*32..+31, cols n_group*64..+63 ----
            const uint32_t Abase = Au + (uint32_t)((j & 1) * (AH_BUF_F * 4));
            #pragma unroll
            for (int kk = 0; kk < 4; kk++) {
                uint4 bb[4];
                #pragma unroll
                for (int rg = 0; rg < 4; rg++)
                    bb[rg] = Bf[kk * 512 + rg * 32];

                uint32_t a[2][4];
                #pragma unroll
                for (int mt = 0; mt < 2; mt++) {
                    uint32_t addr = Abase
                        + (uint32_t)((half * 32 + mt * 16) * (ASTH * 2) + kk * 32)
                        + lm_lane_off;
                    LDMX4(a[mt][0], a[mt][1], a[mt][2], a[mt][3], addr);
                }
                #pragma unroll
                for (int mt = 0; mt < 2; mt++)
                    #pragma unroll
                    for (int rg = 0; rg < 4; rg++) {
                        MMA_F16(acc[mt][2 * rg],
                                a[mt][0], a[mt][1], a[mt][2], a[mt][3],
                                bb[rg].x, bb[rg].y);
                        MMA_F16(acc[mt][2 * rg + 1],
                                a[mt][0], a[mt][1], a[mt][2], a[mt][3],
                                bb[rg].z, bb[rg].w);
                    }
            }

            // ---- LN statistics (packed f32x2) -> sred buf j&1 ----
            ull s1p[2][2], s2p[2][2];
            #pragma unroll
            for (int mt = 0; mt < 2; mt++)
                #pragma unroll
                for (int h = 0; h < 2; h++) { s1p[mt][h] = 0ull; s2p[mt][h] = 0ull; }
            #pragma unroll
            for (int nt = 0; nt < 8; nt++)
                #pragma unroll
                for (int mt = 0; mt < 2; mt++)
                    #pragma unroll
                    for (int h = 0; h < 2; h++) {
                        ull v = pk2(acc[mt][nt][2 * h], acc[mt][nt][2 * h + 1]);
                        s1p[mt][h] = f2add(s1p[mt][h], v);
                        s2p[mt][h] = f2fma(v, v, s2p[mt][h]);
                    }
            float s1[2][2], s2[2][2];
            #pragma unroll
            for (int mt = 0; mt < 2; mt++)
                #pragma unroll
                for (int h = 0; h < 2; h++) {
                    float lo, hi;
                    upk2(s1p[mt][h], lo, hi); s1[mt][h] = lo + hi;
                    upk2(s2p[mt][h], lo, hi); s2[mt][h] = lo + hi;
                }
            #pragma unroll
            for (int o = 1; o <= 2; o <<= 1)
                #pragma unroll
                for (int mt = 0; mt < 2; mt++)
                    #pragma unroll
                    for (int h = 0; h < 2; h++) {
                        s1[mt][h] += __shfl_xor_sync(0xffffffffu, s1[mt][h], o);
                        s2[mt][h] += __shfl_xor_sync(0xffffffffu, s2[mt][h], o);
                    }
            if (tg == 0) {
                float2* sr = sr2 + (j & 1) * SRBUF2;
                #pragma unroll
                for (int mt = 0; mt < 2; mt++)
                    #pragma unroll
                    for (int h = 0; h < 2; h++) {
                        int row = half * 32 + mt * 16 + g + 8 * h;
                        sr[n_group * 64 + row] = make_float2(s1[mt][h], s2[mt][h]);
                    }
            }

            // ---- stage A(j+1) pre-barrier (its old readers done since bar j-1)
            stsA((j + 1) & 1);

            BARH();             // the ONE barrier: sred(j), A(j+1), fred(j-1) visible

            // ---- drain out(j-1) ----
            if (j > 0) out_phase(j - 1);

            // ---- per-row stats from sred(j) ----
            ull rs_p[2][2], off_p[2][2];
            {
                const float2* sr = sr2 + (j & 1) * SRBUF2;
                #pragma unroll
                for (int mt = 0; mt < 2; mt++)
                    #pragma unroll
                    for (int h = 0; h < 2; h++) {
                        int row = half * 32 + mt * 16 + g + 8 * h;
                        float t1 = 0.f, t2 = 0.f;
                        #pragma unroll
                        for (int ng = 0; ng < 4; ng++) {
                            float2 v = sr[ng * 64 + row];
                            t1 += v.x; t2 += v.y;
                        }
                        float m = t1 * (1.0f / 256.0f);
                        float var = fmaf(-m, m, t2 * (1.0f / 256.0f));
                        float rs = rsqrtf(var + 1e-5f);
                        rs_p[mt][h] = pk2(rs, rs);
                        if constexpr (TRIV) {
                            float nr = -m * rs;
                            off_p[mt][h] = pk2(nr, nr);
                        } else {
                            off_p[mt][h] = pk2(-m, -m);
                        }
                    }
            }

            // ---- normalize + relu(cvt-fused) -> fp16 frags -> GEMM2 ----
            float d[2][4] = {{0, 0, 0, 0}, {0, 0, 0, 0}};
            #pragma unroll
            for (int q = 0; q < 4; q++) {
                uint32_t hf[2][2][2];
                #pragma unroll
                for (int p = 0; p < 2; p++) {
                    int nt = 2 * q + p;
                    ull gv = 0, bev = 0;
                    if constexpr (!TRIV) {
                        int colp = n_group * 32 + nt * 4 + tg;
                        float4 pv = reinterpret_cast<const float4*>(pgb)[colp];
                        gv  = pk2(pv.x, pv.y);
                        bev = pk2(pv.z, pv.w);
                    }
                    #pragma unroll
                    for (int mt = 0; mt < 2; mt++)
                        #pragma unroll
                        for (int h = 0; h < 2; h++) {
                            ull ap = pk2(acc[mt][nt][2*h], acc[mt][nt][2*h+1]);
                            ull vp;
                            if constexpr (TRIV) {
                                vp = f2fma(ap, rs_p[mt][h], off_p[mt][h]);
                            } else {
                                ull A = f2mul(rs_p[mt][h], gv);
                                ull B = f2fma(off_p[mt][h], A, bev);
                                vp = f2fma(ap, A, B);
                            }
                            hf[p][mt][h] = h2relu(vp);
                        }
                }
                #pragma unroll
                for (int mt = 0; mt < 2; mt++)
                    MMA_F16(d[mt],
                            hf[0][mt][0], hf[0][mt][1], hf[1][mt][0], hf[1][mt][1],
                            w2f[q][0], w2f[q][1]);
            }

            // ---- store per-n_group partial forces -> fred buf j&1 ----
            if (tg < 2) {
                float* fr = fred + (j & 1) * FRBUF + n_group * 256;
                #pragma unroll
                for (int mt = 0; mt < 2; mt++) {
                    int row0 = half * 32 + mt * 16 + g;
                    if (tg == 0) {
                        fr[row0 * 4 + 0] = d[mt][0];
                        fr[row0 * 4 + 1] = d[mt][1];
                        fr[(row0 + 8) * 4 + 0] = d[mt][2];
                        fr[(row0 + 8) * 4 + 1] = d[mt][3];
                    } else {
                        fr[row0 * 4 + 2] = d[mt][0];
                        fr[(row0 + 8) * 4 + 2] = d[mt][2];
                    }
                }
            }
            // fred(j) consumed after NEXT barrier
        }

        BARH();                 // tail: fred(nT-1) visible
        out_phase(nT - 1);
    };

    if (trivial) runloop(TrueT{});
    else         runloop(FalseT{});
    #undef BARH
}

extern "C" void kernel_launch(void* const* d_in, const int* in_sizes, int n_in,
                              void* d_out, int out_size)
{
    const float* cs    = (const float*)d_in[0];
    const float* W1    = (const float*)d_in[1];
    const float* b1    = (const float*)d_in[2];
    const float* gamma = (const float*)d_in[3];
    const float* beta  = (const float*)d_in[4];
    const float* W2    = (const float*)d_in[5];
    const float* b2    = (const float*)d_in[6];
    float* out = (float*)d_out;

    int dev = 0, sms = 148;
    cudaGetDevice(&dev);
    cudaDeviceGetAttribute(&sms, cudaDevAttrMultiProcessorCount, dev);
    if (sms <= 0) sms = 148;
    int grid = 2 * sms;
    if (grid > T_TILES) grid = T_TILES;

    const size_t smem = SMEM_F * sizeof(float);   // 66576 B
    cudaFuncSetAttribute(motility_mma_kernel,
                         cudaFuncAttributeMaxDynamicSharedMemorySize, (int)smem);
    motility_mma_kernel<<<grid, THREADS, smem>>>(cs, W1, b1, gamma, beta, W2, b2, out);
}

// round 17
// speedup vs baseline: 1.0502x; 1.0502x over previous
#include <cuda_runtime.h>
#include <cuda_fp16.h>
#include <cstdint>

// MotilityModel, fully tensor-core (R13 base, the 76.1us kernel). R17:
// dedicated per-row stat pass (stats computed once per row into a stt table
// instead of 16x redundantly per thread) — cuts ~22 LDS wf/warp/tile and 3
// rsqrt/thread from the epilogue. fp32 A prefetch retained (fp16 prefetch
// correlated with the R15/R16 regressions).
//   h = cs @ W1^T + b1 ; h = LN(h)*gamma+beta ; relu ; out = h @ W2^T + b2
// N=500000, CS=64, H=256, S=3, fp32 in/out.

#define N_CELLS 500000
#define TILE_M  64
#define T_TILES ((N_CELLS + TILE_M - 1) / TILE_M)   // 7813
#define THREADS 256                                  // 8 warps

#define ASTH 72   // A row stride in halfs (144B): ldmatrix conflict-free

// ---- smem layout (float offsets) ----
#define W1F_OFF 0
#define W1F_F   8192                     // 32KB fp16 B fragment-major
#define AH_OFF  (W1F_OFF + W1F_F)        // A fp16 [2][64][ASTH] halfs
#define AH_BUF_F (TILE_M * ASTH / 2)     // 2304 floats per buffer
#define AH_F    (2 * AH_BUF_F)
#define B1_OFF  (AH_OFF + AH_F)          // b1 [256]
#define PGB_OFF (B1_OFF + 256)           // [128 colp] float4 {g0,g1,be0,be1}
#define B2_OFF  (PGB_OFF + 512)
#define SR_OFF  (B2_OFF + 4)             // [4 ng][64 rows] float2 (s1,s2)
#define STT_OFF (SR_OFF + 512)           // [64 rows] float2 stats
#define FR_OFF  (STT_OFF + 128)          // [4 ng][64 rows][4] float
#define SMEM_F  (FR_OFF + 1024)          // 15236 floats = 60944 B

typedef unsigned long long ull;

__device__ __forceinline__ uint32_t h2(float lo, float hi) {
    __half2 h = __floats2half2_rn(lo, hi);
    return *reinterpret_cast<uint32_t*>(&h);
}

// ---- packed f32x2 helpers ----
__device__ __forceinline__ ull pk2(float lo, float hi) {
    ull r; asm("mov.b64 %0, {%1, %2};" : "=l"(r) : "f"(lo), "f"(hi)); return r;
}
__device__ __forceinline__ void upk2(ull p, float& lo, float& hi) {
    asm("mov.b64 {%0, %1}, %2;" : "=f"(lo), "=f"(hi) : "l"(p));
}
__device__ __forceinline__ ull f2fma(ull a, ull b, ull c) {
    ull d; asm("fma.rn.f32x2 %0, %1, %2, %3;" : "=l"(d) : "l"(a), "l"(b), "l"(c)); return d;
}
__device__ __forceinline__ ull f2add(ull a, ull b) {
    ull d; asm("add.rn.f32x2 %0, %1, %2;" : "=l"(d) : "l"(a), "l"(b)); return d;
}
__device__ __forceinline__ ull f2mul(ull a, ull b) {
    ull d; asm("mul.rn.f32x2 %0, %1, %2;" : "=l"(d) : "l"(a), "l"(b)); return d;
}
// relu fused into fp16x2 convert
__device__ __forceinline__ uint32_t h2relu(ull vp) {
    float lo, hi; upk2(vp, lo, hi);
    uint32_t r;
    asm("cvt.rn.relu.f16x2.f32 %0, %1, %2;" : "=r"(r) : "f"(hi), "f"(lo));
    return r;
}

#define MMA_F16(c, a0, a1, a2, a3, bv0, bv1) \
    asm volatile("mma.sync.aligned.m16n8k16.row.col.f32.f16.f16.f32 " \
        "{%0,%1,%2,%3}, {%4,%5,%6,%7}, {%8,%9}, {%0,%1,%2,%3};" \
        : "+f"((c)[0]), "+f"((c)[1]), "+f"((c)[2]), "+f"((c)[3]) \
        : "r"(a0), "r"(a1), "r"(a2), "r"(a3), "r"(bv0), "r"(bv1))

#define LDMX4(r0, r1, r2, r3, addr) \
    asm volatile("ldmatrix.sync.aligned.m8n8.x4.shared.b16 {%0,%1,%2,%3}, [%4];" \
        : "=r"(r0), "=r"(r1), "=r"(r2), "=r"(r3) : "r"(addr))

struct TrueT  { static constexpr bool value = true;  };
struct FalseT { static constexpr bool value = false; };

__global__ void __launch_bounds__(THREADS, 2) motility_mma_kernel(
    const float* __restrict__ cs,   const float* __restrict__ W1,
    const float* __restrict__ b1,   const float* __restrict__ gamma,
    const float* __restrict__ beta, const float* __restrict__ W2,
    const float* __restrict__ b2,   float* __restrict__ out)
{
    extern __shared__ float sm[];
    float* W1f  = sm + W1F_OFF;
    float* b1s  = sm + B1_OFF;
    float* pgb  = sm + PGB_OFF;
    float* b2s  = sm + B2_OFF;
    float* sred = sm + SR_OFF;
    float2* stt = reinterpret_cast<float2*>(sm + STT_OFF);
    float* fred = sm + FR_OFF;

    const int tid  = threadIdx.x;
    const int lane = tid & 31;
    const int warp = tid >> 5;          // 0..7
    const int g    = lane >> 2;         // 0..7
    const int tg   = lane & 3;          // 0..3
    const int half    = warp & 1;       // rows half*32..+31 (own barrier)
    const int n_group = warp >> 1;      // cols n_group*64..+63
    const int hwtid   = n_group * 32 + lane;   // 0..127 within half
    const int bid  = blockIdx.x;
    const int GRID = gridDim.x;

    const int barid = 1 + half;
    #define BARH() asm volatile("bar.sync %0, 128;" :: "r"(barid) : "memory")

    const uint32_t Au = (uint32_t)__cvta_generic_to_shared(sm + AH_OFF);
    const uint32_t lm_lane_off = (uint32_t)(lane & 15) * (ASTH * 2) + (uint32_t)(lane >> 4) * 16;

    const int st_row = half * 32 + (hwtid >> 2);
    const int st_cq  = (hwtid & 3) * 16;
    const uint32_t st_dst = Au + (uint32_t)(st_row * ASTH + st_cq) * 2;

    const int nT = (T_TILES - 1 - bid) / GRID + 1;

    // ---- W2 fp16 B-fragments for GEMM2 ----
    uint32_t w2f[4][2];
    #pragma unroll
    for (int q = 0; q < 4; q++) {
        if (g < 3) {
            const float* wr = W2 + g * 256 + n_group * 64 + q * 16 + tg * 2;
            w2f[q][0] = h2(wr[0], wr[1]);
            w2f[q][1] = h2(wr[8], wr[9]);
        } else {
            w2f[q][0] = 0u; w2f[q][1] = 0u;
        }
    }

    // ---- stage W1 as fp16 fragments (once) ----
    #pragma unroll
    for (int i = 0; i < 8; i++) {
        int idx = tid + i * THREADS;            // 0..2047
        int li  = idx & 31;
        int rg  = (idx >> 5) & 3;
        int ng  = (idx >> 7) & 3;
        int kk  = idx >> 9;
        int gg = li >> 2, tt = li & 3;
        int k0 = kk * 16 + tt * 2;
        int ca = ng * 64 + (rg * 2) * 8 + gg;
        int cb = ca + 8;
        uint4 v;
        v.x = h2(W1[ca * 64 + k0],     W1[ca * 64 + k0 + 1]);
        v.y = h2(W1[ca * 64 + k0 + 8], W1[ca * 64 + k0 + 9]);
        v.z = h2(W1[cb * 64 + k0],     W1[cb * 64 + k0 + 1]);
        v.w = h2(W1[cb * 64 + k0 + 8], W1[cb * 64 + k0 + 9]);
        reinterpret_cast<uint4*>(W1f)[idx] = v;
    }
    b1s[tid] = b1[tid];
    if (tid < 128) {
        int c0 = 2 * tid;
        reinterpret_cast<float4*>(pgb)[tid] =
            make_float4(gamma[c0], gamma[c0 + 1], beta[c0], beta[c0 + 1]);
    }
    if (tid < 3) b2s[tid] = b2[tid];

    // ---- A prefetch in fp32 (16 regs; the fp16 variant regressed) ----
    float4 pf[4];
    auto ldgA = [&](int j) {
        long tile = (long)bid + (long)j * GRID;
        long cell = tile * TILE_M + st_row;
        if (j < nT && cell < N_CELLS) {
            const float4* src = reinterpret_cast<const float4*>(cs + cell * 64 + st_cq);
            pf[0] = src[0]; pf[1] = src[1]; pf[2] = src[2]; pf[3] = src[3];
        } else {
            pf[0] = pf[1] = pf[2] = pf[3] = make_float4(0, 0, 0, 0);
        }
    };
    auto stsA = [&](int buf) {
        uint4 lo, hi;
        lo.x = h2(pf[0].x, pf[0].y); lo.y = h2(pf[0].z, pf[0].w);
        lo.z = h2(pf[1].x, pf[1].y); lo.w = h2(pf[1].z, pf[1].w);
        hi.x = h2(pf[2].x, pf[2].y); hi.y = h2(pf[2].z, pf[2].w);
        hi.z = h2(pf[3].x, pf[3].y); hi.w = h2(pf[3].z, pf[3].w);
        uint32_t d0 = st_dst + (uint32_t)buf * (AH_BUF_F * 4);
        asm volatile("st.shared.v4.b32 [%0], {%1,%2,%3,%4};"
                     :: "r"(d0), "r"(lo.x), "r"(lo.y), "r"(lo.z), "r"(lo.w) : "memory");
        asm volatile("st.shared.v4.b32 [%0], {%1,%2,%3,%4};"
                     :: "r"(d0 + 16), "r"(hi.x), "r"(hi.y), "r"(hi.z), "r"(hi.w) : "memory");
    };

    ldgA(0);
    stsA(0);

    // ---- trivial-affine detection (full-CTA barrier; covers all staging) ----
    int nontriv = (b1[tid] != 0.0f) | (gamma[tid] != 1.0f) | (beta[tid] != 0.0f);
    if (tid < 3) nontriv |= (b2[tid] != 0.0f);
    const bool trivial = (__syncthreads_or(nontriv) == 0);

    const uint4* Bf = reinterpret_cast<const uint4*>(W1f) + n_group * 128 + lane;

    auto runloop = [&](auto trivc) {
        constexpr bool TRIV = decltype(trivc)::value;

        for (int j = 0; j < nT; j++) {
            const long tile = (long)bid + (long)j * GRID;

            // ---- acc init ----
            float acc[2][8][4];
            if constexpr (TRIV) {
                #pragma unroll
                for (int nt = 0; nt < 8; nt++)
                    #pragma unroll
                    for (int mt = 0; mt < 2; mt++)
                        #pragma unroll
                        for (int qq = 0; qq < 4; qq++) acc[mt][nt][qq] = 0.0f;
            } else {
                #pragma unroll
                for (int nt = 0; nt < 8; nt++) {
                    int colp = n_group * 32 + nt * 4 + tg;
                    float2 bv = reinterpret_cast<const float2*>(b1s)[colp];
                    #pragma unroll
                    for (int mt = 0; mt < 2; mt++) {
                        acc[mt][nt][0] = bv.x; acc[mt][nt][1] = bv.y;
                        acc[mt][nt][2] = bv.x; acc[mt][nt][3] = bv.y;
                    }
                }
            }

            // ---- GEMM1: rows half*32..+31, cols n_group*64..+63 ----
            const uint32_t Abase = Au + (uint32_t)((j & 1) * (AH_BUF_F * 4));
            #pragma unroll
            for (int kk = 0; kk < 4; kk++) {
                uint4 bb[4];
                #pragma unroll
                for (int rg = 0; rg < 4; rg++)
                    bb[rg] = Bf[kk * 512 + rg * 32];

                uint32_t a[2][4];
                #pragma unroll
                for (int mt = 0; mt < 2; mt++) {
                    uint32_t addr = Abase
                        + (uint32_t)((half * 32 + mt * 16) * (ASTH * 2) + kk * 32)
                        + lm_lane_off;
                    LDMX4(a[mt][0], a[mt][1], a[mt][2], a[mt][3], addr);
                }
                #pragma unroll
                for (int mt = 0; mt < 2; mt++)
                    #pragma unroll
                    for (int rg = 0; rg < 4; rg++) {
                        MMA_F16(acc[mt][2 * rg],
                                a[mt][0], a[mt][1], a[mt][2], a[mt][3],
                                bb[rg].x, bb[rg].y);
                        MMA_F16(acc[mt][2 * rg + 1],
                                a[mt][0], a[mt][1], a[mt][2], a[mt][3],
                                bb[rg].z, bb[rg].w);
                    }
            }

            // ---- prefetch next A tile (own half's rows) ----
            ldgA(j + 1);

            // ---- LN statistics (packed f32x2) ----
            ull s1p[2][2], s2p[2][2];
            #pragma unroll
            for (int mt = 0; mt < 2; mt++)
                #pragma unroll
                for (int h = 0; h < 2; h++) { s1p[mt][h] = 0ull; s2p[mt][h] = 0ull; }
            #pragma unroll
            for (int nt = 0; nt < 8; nt++)
                #pragma unroll
                for (int mt = 0; mt < 2; mt++)
                    #pragma unroll
                    for (int h = 0; h < 2; h++) {
                        ull v = pk2(acc[mt][nt][2 * h], acc[mt][nt][2 * h + 1]);
                        s1p[mt][h] = f2add(s1p[mt][h], v);
                        s2p[mt][h] = f2fma(v, v, s2p[mt][h]);
                    }
            float s1[2][2], s2[2][2];
            #pragma unroll
            for (int mt = 0; mt < 2; mt++)
                #pragma unroll
                for (int h = 0; h < 2; h++) {
                    float lo, hi;
                    upk2(s1p[mt][h], lo, hi); s1[mt][h] = lo + hi;
                    upk2(s2p[mt][h], lo, hi); s2[mt][h] = lo + hi;
                }
            #pragma unroll
            for (int o = 1; o <= 2; o <<= 1)
                #pragma unroll
                for (int mt = 0; mt < 2; mt++)
                    #pragma unroll
                    for (int h = 0; h < 2; h++) {
                        s1[mt][h] += __shfl_xor_sync(0xffffffffu, s1[mt][h], o);
                        s2[mt][h] += __shfl_xor_sync(0xffffffffu, s2[mt][h], o);
                    }
            if (tg == 0) {
                #pragma unroll
                for (int mt = 0; mt < 2; mt++)
                    #pragma unroll
                    for (int h = 0; h < 2; h++) {
                        int row = half * 32 + mt * 16 + g + 8 * h;
                        reinterpret_cast<float2*>(sred)[n_group * 64 + row] =
                            make_float2(s1[mt][h], s2[mt][h]);
                    }
            }
            BARH();             // SYNC1 (per half): sred visible

            // ---- stat pass: one thread per row of this half (32 threads) ----
            if (hwtid < 32) {
                int row = half * 32 + hwtid;
                float t1 = 0.f, t2 = 0.f;
                #pragma unroll
                for (int ng = 0; ng < 4; ng++) {
                    float2 v = reinterpret_cast<const float2*>(sred)[ng * 64 + row];
                    t1 += v.x; t2 += v.y;
                }
                float m = t1 * (1.0f / 256.0f);
                float var = fmaf(-m, m, t2 * (1.0f / 256.0f));
                float rs = rsqrtf(var + 1e-5f);
                if constexpr (TRIV)
                    stt[row] = make_float2(rs, -m * rs);
                else
                    stt[row] = make_float2(rs, -m);
            }
            BARH();             // SYNC1b (per half): stt visible

            // ---- per-lane stats for its 4 rows (4 LDS.64) ----
            ull rs_p[2][2], off_p[2][2];
            #pragma unroll
            for (int mt = 0; mt < 2; mt++)
                #pragma unroll
                for (int h = 0; h < 2; h++) {
                    int row = half * 32 + mt * 16 + g + 8 * h;
                    float2 sv = stt[row];
                    rs_p[mt][h]  = pk2(sv.x, sv.x);
                    off_p[mt][h] = pk2(sv.y, sv.y);   // TRIV: -mu*rs ; else: -mu
                }

            // ---- normalize + relu(cvt-fused) -> fp16 frags -> GEMM2 MMA ----
            float d[2][4] = {{0, 0, 0, 0}, {0, 0, 0, 0}};
            #pragma unroll
            for (int q = 0; q < 4; q++) {
                uint32_t hf[2][2][2];
                #pragma unroll
                for (int p = 0; p < 2; p++) {
                    int nt = 2 * q + p;
                    ull gv = 0, bev = 0;
                    if constexpr (!TRIV) {
                        int colp = n_group * 32 + nt * 4 + tg;
                        float4 pv = reinterpret_cast<const float4*>(pgb)[colp];
                        gv  = pk2(pv.x, pv.y);
                        bev = pk2(pv.z, pv.w);
                    }
                    #pragma unroll
                    for (int mt = 0; mt < 2; mt++)
                        #pragma unroll
                        for (int h = 0; h < 2; h++) {
                            ull ap = pk2(acc[mt][nt][2*h], acc[mt][nt][2*h+1]);
                            ull vp;
                            if constexpr (TRIV) {
                                vp = f2fma(ap, rs_p[mt][h], off_p[mt][h]);
                            } else {
                                // (acc*rs + (-mu)*rs)*gamma + beta
                                ull A = f2mul(rs_p[mt][h], gv);
                                ull B = f2fma(off_p[mt][h], A, bev);
                                vp = f2fma(ap, A, B);
                            }
                            hf[p][mt][h] = h2relu(vp);
                        }
                }
                #pragma unroll
                for (int mt = 0; mt < 2; mt++)
                    MMA_F16(d[mt],
                            hf[0][mt][0], hf[0][mt][1], hf[1][mt][0], hf[1][mt][1],
                            w2f[q][0], w2f[q][1]);
            }

            // ---- store per-n_group partial forces (rows of this half) ----
            if (tg < 2) {
                #pragma unroll
                for (int mt = 0; mt < 2; mt++) {
                    int row0 = half * 32 + mt * 16 + g;
                    float* fr = fred + n_group * 256;
                    if (tg == 0) {
                        fr[row0 * 4 + 0] = d[mt][0];
                        fr[row0 * 4 + 1] = d[mt][1];
                        fr[(row0 + 8) * 4 + 0] = d[mt][2];
                        fr[(row0 + 8) * 4 + 1] = d[mt][3];
                    } else {
                        fr[row0 * 4 + 2] = d[mt][0];
                        fr[(row0 + 8) * 4 + 2] = d[mt][2];
                    }
                }
            }
            stsA((j + 1) & 1);  // write next A buffer (own half's rows)
            BARH();             // SYNC2 (per half): fred + A(j+1) rows visible

            if (hwtid < 96) {
                int row = half * 32 + hwtid / 3;
                int s   = hwtid - (hwtid / 3) * 3;
                long cell = tile * TILE_M + row;
                if (cell < N_CELLS) {
                    float v = fred[row * 4 + s] + fred[256 + row * 4 + s]
                            + fred[512 + row * 4 + s] + fred[768 + row * 4 + s];
                    if constexpr (!TRIV) v += b2s[s];
                    out[tile * (TILE_M * 3) + row * 3 + s] = v;
                }
            }
        }
    };

    if (trivial) runloop(TrueT{});
    else         runloop(FalseT{});
    #undef BARH
}

extern "C" void kernel_launch(void* const* d_in, const int* in_sizes, int n_in,
                              void* d_out, int out_size)
{
    const float* cs    = (const float*)d_in[0];
    const float* W1    = (const float*)d_in[1];
    const float* b1    = (const float*)d_in[2];
    const float* gamma = (const float*)d_in[3];
    const float* beta  = (const float*)d_in[4];
    const float* W2    = (const float*)d_in[5];
    const float* b2    = (const float*)d_in[6];
    float* out = (float*)d_out;

    int dev = 0, sms = 148;
    cudaGetDevice(&dev);
    cudaDeviceGetAttribute(&sms, cudaDevAttrMultiProcessorCount, dev);
    if (sms <= 0) sms = 148;
    int grid = 2 * sms;
    if (grid > T_TILES) grid = T_TILES;

    const size_t smem = SMEM_F * sizeof(float);   // 60944 B
    cudaFuncSetAttribute(motility_mma_kernel,
                         cudaFuncAttributeMaxDynamicSharedMemorySize, (int)smem);
    motility_mma_kernel<<<grid, THREADS, smem>>>(cs, W1, b1, gamma, beta, W2, b2, out);
}